// round 9
// baseline (speedup 1.0000x reference)
#include <cuda_runtime.h>

#define NN 1024
#define DD 128
#define NL 3
#define NBLK 256
#define NTHR 256

typedef unsigned long long u64;

// ---------------- f32x2 helpers ----------------
__device__ __forceinline__ u64 pack2(float x, float y){ u64 r; asm("mov.b64 %0,{%1,%2};":"=l"(r):"f"(x),"f"(y)); return r; }
__device__ __forceinline__ u64 dup2(float x){ return pack2(x,x); }
__device__ __forceinline__ u64 fma2(u64 a,u64 b,u64 c){ u64 d; asm("fma.rn.f32x2 %0,%1,%2,%3;":"=l"(d):"l"(a),"l"(b),"l"(c)); return d; }
__device__ __forceinline__ u64 add2(u64 a,u64 b){ u64 d; asm("add.rn.f32x2 %0,%1,%2;":"=l"(d):"l"(a),"l"(b)); return d; }
__device__ __forceinline__ float2 unpk(u64 x){ float2 f; asm("mov.b64 {%0,%1},%2;":"=f"(f.x),"=f"(f.y):"l"(x)); return f; }

// ---------------- scratch ----------------
__device__ float g_h  [NN*DD];
__device__ float g_v  [NN*DD];
__device__ float g_tp [NN*DD];       // tpre = h@Wug + b2
__device__ float g_hi [NN*DD];
__device__ float g_hjb[NN*DD];
__device__ float g_P  [8][NN*DD];    // agg split-K partials
__device__ float g_Wug[NL][DD*DD];
__device__ float g_b2 [NL][DD];
__device__ float g_part[NBLK];
__device__ unsigned g_cnt;
__device__ volatile unsigned g_gen;

// ---------------- shared memory union ----------------
struct SMg { float As[32][20]; float Bs[32][128]; };
struct SMa { float As[32][68]; float Bs[32][128]; };
struct SMd { float AsT[128][18]; float Bs[32][128]; };
struct SMc { float hiS[64][34]; float hjS[64][34]; u64 ws[64];
             float si[64]; float sj[64]; float red[256]; };
union SMu { SMg g; SMa a; SMd d; SMc c; };

// ---------------- software grid barrier (all NBLK blocks co-resident) ----------------
__device__ __forceinline__ void gsync(){
    __syncthreads();
    if (threadIdx.x == 0){
        unsigned gen = g_gen;
        __threadfence();
        if (atomicAdd(&g_cnt, 1u) == NBLK - 1u){
            g_cnt = 0u;
            __threadfence();
            g_gen = gen + 1u;
        } else {
            while (g_gen == gen) { }
        }
        __threadfence();
    }
    __syncthreads();
}

// ---------------- 16-row x 128-col GEMM tile, K=128, f32x2 ----------------
__device__ void gemm16(SMg& s, const float* __restrict__ A, int lda,
                       const float* __restrict__ B,
                       const float* __restrict__ bias,
                       float* __restrict__ O)
{
    int t = threadIdx.x;
    int r0 = (t>>5)*2, c0 = (t&31)*4;
    u64 a00=0ull, a01=0ull, a10=0ull, a11=0ull;
    for (int kb = 0; kb < DD; kb += 32){
        __syncthreads();
        if (t < 128){
            int r = t>>3, f4 = t&7;
            float4 v = *(const float4*)&A[(size_t)r*lda + kb + f4*4];
            s.As[f4*4+0][r]=v.x; s.As[f4*4+1][r]=v.y;
            s.As[f4*4+2][r]=v.z; s.As[f4*4+3][r]=v.w;
        }
#pragma unroll
        for (int e=0;e<4;e++){
            int idx=e*256+t; int k=idx>>5, c4=idx&31;
            *(float4*)&s.Bs[k][c4*4] = *(const float4*)&B[(size_t)(kb+k)*DD + c4*4];
        }
        __syncthreads();
#pragma unroll
        for (int k=0;k<32;k++){
            float2 a2 = *(const float2*)&s.As[k][r0];
            ulonglong2 b = *(const ulonglong2*)&s.Bs[k][c0];
            u64 d0=dup2(a2.x), d1=dup2(a2.y);
            a00=fma2(d0,b.x,a00); a01=fma2(d0,b.y,a01);
            a10=fma2(d1,b.x,a10); a11=fma2(d1,b.y,a11);
        }
    }
    u64 bb0=0ull, bb1=0ull;
    if (bias){ float4 u=*(const float4*)&bias[c0]; bb0=pack2(u.x,u.y); bb1=pack2(u.z,u.w); }
    ulonglong2 sv;
    sv.x=add2(a00,bb0); sv.y=add2(a01,bb1);
    *(ulonglong2*)&O[(size_t)r0*DD + c0] = sv;
    sv.x=add2(a10,bb0); sv.y=add2(a11,bb1);
    *(ulonglong2*)&O[(size_t)(r0+1)*DD + c0] = sv;
}

// ---------------- the persistent kernel ----------------
__global__ __launch_bounds__(NTHR, 2) void persist_kernel(
    const float* __restrict__ nf,  const float* __restrict__ adj,
    const float* __restrict__ ew,  const float* __restrict__ We,
    const float* __restrict__ be,  const float* __restrict__ Wu,
    const float* __restrict__ bu,  const float* __restrict__ Wv,
    const float* __restrict__ bv,  const float* __restrict__ Wg,
    const float* __restrict__ bg,  const float* __restrict__ Wc1,
    const float* __restrict__ bc1, const float* __restrict__ Wc2,
    const float* __restrict__ bc2, float* __restrict__ out, int has_loss)
{
    __shared__ SMu sm;
    int t = threadIdx.x, bid = blockIdx.x;

    // ===== Stage A: weight fold (Wug = Wu@Wg1, b2 = bu@Wg1 + bg) + embed =====
    if (bid < 24){
        int l = bid>>3, rb = (bid&7)*16;
        gemm16(sm.g, Wu + (size_t)l*DD*DD + rb*DD, DD, Wg + (size_t)l*2*DD*DD,
               nullptr, &g_Wug[l][rb*DD]);
    } else if (bid < 27){
        int l = bid - 24;
        if (t < DD){
            float acc = 0.f;
            const float* bl = bu + l*DD;
            const float* w  = Wg + (size_t)l*2*DD*DD;
#pragma unroll 4
            for (int d=0; d<DD; d++) acc = fmaf(bl[d], w[(size_t)d*DD + t], acc);
            g_b2[l][t] = acc + bg[l*DD + t];
        }
    } else {
        for (int idx = (bid-27)*NTHR + t; idx < NN*DD; idx += 229*NTHR){
            int i = idx>>7, dd = idx&127;
            float a0=nf[3*i], a1=nf[3*i+1], a2=nf[3*i+2];
            g_h[idx] = be[dd] + a0*We[dd] + a1*We[DD+dd] + a2*We[2*DD+dd];
        }
    }
    gsync();

    for (int l = 0; l < NL; l++){
        // ===== Stage B: v = h@Wv + bv ; tpre = h@Wug + b2  (128 tiles) =====
        if (bid < 128){
            int sel = bid>>6, rb = (bid&63)*16;
            if (sel == 0)
                gemm16(sm.g, g_h + (size_t)rb*DD, DD, Wv + (size_t)l*DD*DD,
                       bv + l*DD, g_v + (size_t)rb*DD);
            else
                gemm16(sm.g, g_h + (size_t)rb*DD, DD, g_Wug[l],
                       g_b2[l], g_tp + (size_t)rb*DD);
        }
        gsync();

        // ===== Stage C: agg split-K partials = adj@v  (128 tiles: 16 row x 8 K) =====
        if (bid < 128){
            int ks = bid>>4, rb = (bid&15)*64, kst = ks*128;
            const float* Ab = adj + (size_t)rb*NN + kst;
            int r0 = (t>>5)*8, c0 = (t&31)*4;
            u64 acc[8][2];
#pragma unroll
            for (int r=0;r<8;r++){ acc[r][0]=0ull; acc[r][1]=0ull; }
            for (int kb=0; kb<128; kb+=32){
                __syncthreads();
#pragma unroll
                for (int e=0;e<2;e++){
                    int idx=e*256+t; int r=idx>>3, f4=idx&7;
                    float4 v = *(const float4*)&Ab[(size_t)r*NN + kb + f4*4];
                    sm.a.As[f4*4+0][r]=v.x; sm.a.As[f4*4+1][r]=v.y;
                    sm.a.As[f4*4+2][r]=v.z; sm.a.As[f4*4+3][r]=v.w;
                }
#pragma unroll
                for (int e=0;e<4;e++){
                    int idx=e*256+t; int k=idx>>5, c4=idx&31;
                    *(float4*)&sm.a.Bs[k][c4*4] =
                        *(const float4*)&g_v[(size_t)(kst+kb+k)*DD + c4*4];
                }
                __syncthreads();
#pragma unroll
                for (int k=0;k<32;k++){
                    float4 x=*(const float4*)&sm.a.As[k][r0];
                    float4 y=*(const float4*)&sm.a.As[k][r0+4];
                    ulonglong2 b=*(const ulonglong2*)&sm.a.Bs[k][c0];
                    u64 d0=dup2(x.x),d1=dup2(x.y),d2=dup2(x.z),d3=dup2(x.w);
                    u64 d4=dup2(y.x),d5=dup2(y.y),d6=dup2(y.z),d7=dup2(y.w);
                    acc[0][0]=fma2(d0,b.x,acc[0][0]); acc[0][1]=fma2(d0,b.y,acc[0][1]);
                    acc[1][0]=fma2(d1,b.x,acc[1][0]); acc[1][1]=fma2(d1,b.y,acc[1][1]);
                    acc[2][0]=fma2(d2,b.x,acc[2][0]); acc[2][1]=fma2(d2,b.y,acc[2][1]);
                    acc[3][0]=fma2(d3,b.x,acc[3][0]); acc[3][1]=fma2(d3,b.y,acc[3][1]);
                    acc[4][0]=fma2(d4,b.x,acc[4][0]); acc[4][1]=fma2(d4,b.y,acc[4][1]);
                    acc[5][0]=fma2(d5,b.x,acc[5][0]); acc[5][1]=fma2(d5,b.y,acc[5][1]);
                    acc[6][0]=fma2(d6,b.x,acc[6][0]); acc[6][1]=fma2(d6,b.y,acc[6][1]);
                    acc[7][0]=fma2(d7,b.x,acc[7][0]); acc[7][1]=fma2(d7,b.y,acc[7][1]);
                }
            }
            float* P = &g_P[ks][(size_t)(rb+r0)*DD + c0];
#pragma unroll
            for (int r=0;r<8;r++){
                ulonglong2 s2; s2.x=acc[r][0]; s2.y=acc[r][1];
                *(ulonglong2*)(P + (size_t)r*DD) = s2;
            }
        }
        gsync();

        // ===== Stage D: t = tpre + agg@Wg2 ; h = relu(h + sigmoid(t)*agg) (64 tiles) =====
        if (bid < 64){
            int rb = bid*16;
            // stage summed agg (8 partial slabs) transposed into AsT[k][r]
#pragma unroll
            for (int e=0;e<2;e++){
                int idx=e*256+t;              // 512 float4
                int r=idx>>5, k4=idx&31;
                size_t off = (size_t)(rb+r)*DD + k4*4;
                float4 s0 = *(const float4*)&g_P[0][off];
#pragma unroll
                for (int z=1; z<8; z++){
                    float4 p = *(const float4*)&g_P[z][off];
                    s0.x+=p.x; s0.y+=p.y; s0.z+=p.z; s0.w+=p.w;
                }
                sm.d.AsT[k4*4+0][r]=s0.x; sm.d.AsT[k4*4+1][r]=s0.y;
                sm.d.AsT[k4*4+2][r]=s0.z; sm.d.AsT[k4*4+3][r]=s0.w;
            }
            int r0=(t>>5)*2, c0=(t&31)*4;
            u64 a00=0ull,a01=0ull,a10=0ull,a11=0ull;
            const float* Wg2 = Wg + (size_t)l*2*DD*DD + DD*DD;
            for (int kb=0; kb<128; kb+=32){
                __syncthreads();
#pragma unroll
                for (int e=0;e<4;e++){
                    int idx=e*256+t; int k=idx>>5, c4=idx&31;
                    *(float4*)&sm.d.Bs[k][c4*4] =
                        *(const float4*)&Wg2[(size_t)(kb+k)*DD + c4*4];
                }
                __syncthreads();
#pragma unroll
                for (int k=0;k<32;k++){
                    float2 a2=*(const float2*)&sm.d.AsT[kb+k][r0];
                    ulonglong2 b=*(const ulonglong2*)&sm.d.Bs[k][c0];
                    u64 d0=dup2(a2.x), d1=dup2(a2.y);
                    a00=fma2(d0,b.x,a00); a01=fma2(d0,b.y,a01);
                    a10=fma2(d1,b.x,a10); a11=fma2(d1,b.y,a11);
                }
            }
            // epilogue (AsT holds agg; only read, no sync needed)
            {
                size_t off0 = (size_t)(rb+r0)*DD + c0;
                size_t off1 = (size_t)(rb+r0+1)*DD + c0;
                float4 tp0 = *(const float4*)&g_tp[off0];
                float4 tp1 = *(const float4*)&g_tp[off1];
                float4 h0  = *(const float4*)&g_h[off0];
                float4 h1  = *(const float4*)&g_h[off1];
                float2 p;
                float tt0[4], tt1[4];
                p=unpk(a00); tt0[0]=p.x+tp0.x; tt0[1]=p.y+tp0.y;
                p=unpk(a01); tt0[2]=p.x+tp0.z; tt0[3]=p.y+tp0.w;
                p=unpk(a10); tt1[0]=p.x+tp1.x; tt1[1]=p.y+tp1.y;
                p=unpk(a11); tt1[2]=p.x+tp1.z; tt1[3]=p.y+tp1.w;
                float hh0[4]={h0.x,h0.y,h0.z,h0.w};
                float hh1[4]={h1.x,h1.y,h1.z,h1.w};
                float o0[4], o1[4];
#pragma unroll
                for (int q=0;q<4;q++){
                    float ag0 = sm.d.AsT[c0+q][r0];
                    float ag1 = sm.d.AsT[c0+q][r0+1];
                    float gv0 = 1.f/(1.f+__expf(-tt0[q]));
                    float gv1 = 1.f/(1.f+__expf(-tt1[q]));
                    o0[q] = fmaxf(hh0[q] + gv0*ag0, 0.f);
                    o1[q] = fmaxf(hh1[q] + gv1*ag1, 0.f);
                }
                *(float4*)&g_h[off0] = make_float4(o0[0],o0[1],o0[2],o0[3]);
                *(float4*)&g_h[off1] = make_float4(o1[0],o1[1],o1[2],o1[3]);
            }
        }
        gsync();
    }

    // ===== Stage E: hi = h@Wc1a ; hjb = h@Wc1b + bc1  (128 tiles) =====
    if (bid < 128){
        int sel = bid>>6, rb = (bid&63)*16;
        if (sel == 0)
            gemm16(sm.g, g_h + (size_t)rb*DD, DD, Wc1, nullptr, g_hi + (size_t)rb*DD);
        else
            gemm16(sm.g, g_h + (size_t)rb*DD, DD, Wc1 + DD*DD, bc1, g_hjb + (size_t)rb*DD);
    }
    gsync();

    // ===== Stage F: classifier + loss partials  (256 tiles of 64x64) =====
    {
        int ib = (bid>>4)*64, jb = (bid&15)*64;

        if (t < 128){
            const float* row = (t < 64) ? &g_hi[(size_t)(ib + t)*DD]
                                        : &g_hjb[(size_t)(jb + t - 64)*DD];
            float s0=0.f,s1=0.f,s2=0.f,s3=0.f;
#pragma unroll
            for (int h = 0; h < DD; h += 4){
                float4 v = *(const float4*)&row[h];
                float4 w = *(const float4*)&Wc2[h];
                s0=fmaf(v.x,w.x,s0); s1=fmaf(v.y,w.y,s1);
                s2=fmaf(v.z,w.z,s2); s3=fmaf(v.w,w.w,s3);
            }
            float s = 0.5f*((s0+s1)+(s2+s3));
            if (t < 64) sm.c.si[t]      = s;
            else        sm.c.sj[t - 64] = s + bc2[0];
        } else if (t < 192){
            int h2 = t - 128;
            sm.c.ws[h2] = pack2(0.5f*Wc2[2*h2], 0.5f*Wc2[2*h2+1]);
        }

        int ig = t >> 4, jg = t & 15;
        const u64 amask = 0x7FFFFFFF7FFFFFFFull;

        u64 acc[4][4];
#pragma unroll
        for (int a=0;a<4;a++)
#pragma unroll
            for (int b=0;b<4;b++) acc[a][b]=0ull;

        for (int hc = 0; hc < DD; hc += 32){
            __syncthreads();
#pragma unroll
            for (int e=0;e<4;e++){
                int idx=e*256+t;
                int r=idx>>4, q=(idx&15)*2;
                *(float2*)&sm.c.hiS[r][q] = *(const float2*)&g_hi [(size_t)(ib+r)*DD + hc + q];
                *(float2*)&sm.c.hjS[r][q] = *(const float2*)&g_hjb[(size_t)(jb+r)*DD + hc + q];
            }
            __syncthreads();
#pragma unroll
            for (int hp=0; hp<16; hp++){
                u64 wp = sm.c.ws[(hc>>1)+hp];
                u64 ai[4], bj[4];
#pragma unroll
                for (int a=0;a<4;a++){
                    ai[a] = *(const u64*)&sm.c.hiS[ig + a*16][hp*2];
                    bj[a] = *(const u64*)&sm.c.hjS[jg + a*16][hp*2];
                }
#pragma unroll
                for (int a=0;a<4;a++)
#pragma unroll
                    for (int b=0;b<4;b++){
                        u64 s = add2(ai[a], bj[b]) & amask;
                        acc[a][b] = fma2(s, wp, acc[a][b]);
                    }
            }
        }

        float lsum = 0.f;
#pragma unroll
        for (int a=0;a<4;a++){
            int i = ib + ig + a*16;
            float sia = sm.c.si[ig + a*16];
#pragma unroll
            for (int b=0;b<4;b++){
                int j = jb + jg + b*16;
                float2 p = unpk(acc[a][b]);
                float lg = (p.x + p.y) + sia + sm.c.sj[jg + b*16];
                size_t off = (size_t)i*NN + j;
                out[off] = lg;
                float d = lg*adj[off] - ew[off];
                lsum = fmaf(d, d, lsum);
            }
        }

        sm.c.red[t] = lsum;
        __syncthreads();
#pragma unroll
        for (int s=128; s>0; s>>=1){
            if (t < s) sm.c.red[t] += sm.c.red[t+s];
            __syncthreads();
        }
        if (t == 0) g_part[bid] = sm.c.red[0];
    }
    gsync();

    // ===== Stage G: final deterministic loss reduce =====
    if (has_loss && bid == 0){
        sm.c.red[t] = g_part[t];
        __syncthreads();
#pragma unroll
        for (int s=128; s>0; s>>=1){
            if (t < s) sm.c.red[t] += sm.c.red[t+s];
            __syncthreads();
        }
        if (t == 0) out[NN*NN] = sm.c.red[0] * (1.f/(1024.f*1024.f));
    }
}

// ---------------- launch ----------------
extern "C" void kernel_launch(void* const* d_in, const int* in_sizes, int n_in,
                              void* d_out, int out_size)
{
    const float* nf   = (const float*)d_in[0];
    const float* adj  = (const float*)d_in[1];
    const float* ew   = (const float*)d_in[2];
    const float* We   = (const float*)d_in[3];
    const float* be   = (const float*)d_in[4];
    const float* Wu   = (const float*)d_in[5];
    const float* bu   = (const float*)d_in[6];
    const float* Wv   = (const float*)d_in[7];
    const float* bv   = (const float*)d_in[8];
    const float* Wg   = (const float*)d_in[9];
    const float* bg   = (const float*)d_in[10];
    const float* Wc1  = (const float*)d_in[11];
    const float* bc1  = (const float*)d_in[12];
    const float* Wc2  = (const float*)d_in[13];
    const float* bc2  = (const float*)d_in[14];
    float* out = (float*)d_out;

    int has_loss = (out_size > NN*NN) ? 1 : 0;

    persist_kernel<<<NBLK, NTHR>>>(nf, adj, ew, We, be, Wu, bu, Wv, bv,
                                   Wg, bg, Wc1, bc1, Wc2, bc2, out, has_loss);
}